// round 6
// baseline (speedup 1.0000x reference)
#include <cuda_runtime.h>
#include <cuda_bf16.h>
#include <cuda_fp8.h>
#include <stdint.h>
#include <stddef.h>

#define DIM   1024
#define BQ    2048
#define CC    65536
#define KSEL  8
#define KCAND 32
#define NTILE (CC / 128)        // 512 key tiles per query
#define PER_TILE 8              // candidates kept per (query, tile)

// ---------------- fp8 GEMM geometry ----------------
#define BM 128
#define BN 128
#define BKB 64                  // 64 fp8 bytes of K per chunk
#define NCHUNK (DIM / BKB)      // 16
#define LDSB 80                 // smem row stride in bytes (64 + 16 pad)
#define STAGE_BYTES (2 * BM * LDSB)   // A + B : 20480 B
#define STAGES 3
#define SMEM_DYN (STAGES * STAGE_BYTES)   // 61440 (also reused for the 128x136 sims tile: 34816 B)
#define SIMS_STRIDE 136         // uint16 elements per sims row (128 + 8 pad; even, 8B-aligned rows)

// ---------------- scratch (device globals; no allocations allowed) ----------------
static __device__ uint8_t  g_Qf8[(size_t)BQ * DIM];               // 2 MB   (raw query, e4m3)
static __device__ uint8_t  g_Kf8[(size_t)CC * DIM];               // 64 MB  (16*normalized keys, e4m3)
static __device__ float    g_rnorm[CC];                           // 256 KB
static __device__ uint32_t g_part[(size_t)BQ * NTILE * PER_TILE]; // 32 MB  (mono16<<16 | col)
static __device__ int      g_cand[BQ * KCAND];                    // 256 KB

// ---------------- helpers ----------------
__device__ __forceinline__ void cp_async16(void* smem, const void* gmem) {
    uint32_t s = (uint32_t)__cvta_generic_to_shared(smem);
    asm volatile("cp.async.cg.shared.global [%0], [%1], 16;\n" :: "r"(s), "l"(gmem) : "memory");
}
#define CP_COMMIT() asm volatile("cp.async.commit_group;\n" ::: "memory")

// pack 4 floats -> 4 e4m3 bytes (byte i = x[i])
__device__ __forceinline__ uint32_t pack_e4m3x4(float x0, float x1, float x2, float x3) {
    uint16_t lo, hi;
    asm("cvt.rn.satfinite.e4m3x2.f32 %0, %1, %2;" : "=h"(lo) : "f"(x1), "f"(x0));
    asm("cvt.rn.satfinite.e4m3x2.f32 %0, %1, %2;" : "=h"(hi) : "f"(x3), "f"(x2));
    return (uint32_t)lo | ((uint32_t)hi << 16);
}

__device__ __forceinline__ void mma_e4m3(float* d, const uint32_t* a, const uint32_t* b) {
    asm volatile(
        "mma.sync.aligned.m16n8k32.row.col.f32.e4m3.e4m3.f32 "
        "{%0,%1,%2,%3}, {%4,%5,%6,%7}, {%8,%9}, {%0,%1,%2,%3};\n"
        : "+f"(d[0]), "+f"(d[1]), "+f"(d[2]), "+f"(d[3])
        : "r"(a[0]), "r"(a[1]), "r"(a[2]), "r"(a[3]), "r"(b[0]), "r"(b[1]));
}

// float -> bf16 bits -> order-preserving uint16 (larger float => larger uint)
__device__ __forceinline__ uint32_t mono16(float x) {
    uint16_t b = __bfloat16_as_ushort(__float2bfloat16(x));
    return (b & 0x8000u) ? (uint32_t)(uint16_t)~b : (uint32_t)(b | 0x8000u);
}

// ---------------- prep: query -> e4m3 ----------------
__global__ void prep_q_kernel(const float4* __restrict__ q) {
    int i = blockIdx.x * blockDim.x + threadIdx.x;   // over BQ*DIM/4
    float4 v = q[i];
    ((uint32_t*)g_Qf8)[i] = pack_e4m3x4(v.x, v.y, v.z, v.w);
}

// ---------------- prep: keys -> 16 * normalized e4m3 + inverse norms ----------------
__global__ void prep_keys_kernel(const float* __restrict__ keys) {
    int row = blockIdx.x;
    int t = threadIdx.x, lane = t & 31, w = t >> 5;
    const float4* kr = (const float4*)(keys + (size_t)row * DIM);   // 256 float4 per row
    float4 v = kr[t];
    float ss = v.x*v.x + v.y*v.y + v.z*v.z + v.w*v.w;
    #pragma unroll
    for (int o = 16; o; o >>= 1) ss += __shfl_xor_sync(0xFFFFFFFFu, ss, o);
    __shared__ float sred[8];
    __shared__ float srn;
    if (lane == 0) sred[w] = ss;
    __syncthreads();
    if (t == 0) {
        float tot = 0.f;
        #pragma unroll
        for (int j = 0; j < 8; j++) tot += sred[j];
        float rn = 1.0f / fmaxf(sqrtf(tot), 1e-12f);
        g_rnorm[row] = rn;
        srn = rn * 16.0f;       // scale into e4m3 sweet spot (monotone per-column factor)
    }
    __syncthreads();
    float rn = srn;
    ((uint32_t*)(g_Kf8 + (size_t)row * DIM))[t] =
        pack_e4m3x4(v.x * rn, v.y * rn, v.z * rn, v.w * rn);
}

// ---------------- fp8 GEMM fused with per-tile top-8 selection ----------------
__global__ __launch_bounds__(256, 2) void gemm_kernel() {
    extern __shared__ uint8_t smem[];

    const int tid = threadIdx.x;
    const int m0 = blockIdx.y * BM;
    const int n0 = blockIdx.x * BN;
    const int warp = tid >> 5, lane = tid & 31;
    const int wm = (warp & 1) * 64;     // 2 warps in M (64 rows each)
    const int wn = (warp >> 1) * 32;    // 4 warps in N (32 cols each)

    float acc[4][4][4];
    #pragma unroll
    for (int i = 0; i < 4; i++)
        #pragma unroll
        for (int j = 0; j < 4; j++)
            #pragma unroll
            for (int r = 0; r < 4; r++) acc[i][j][r] = 0.f;

    // stage layout: A rows [0,128) then B rows [0,128), each LDSB bytes
#define LOAD_CHUNK(st, kt) do {                                                        \
        uint8_t* base_ = smem + (st) * STAGE_BYTES;                                    \
        int kb_ = (kt) * BKB;                                                          \
        _Pragma("unroll")                                                              \
        for (int h = 0; h < 4; h++) {                                                  \
            int e_ = tid + (h << 8);          /* 0..1023 */                            \
            int row_ = e_ >> 2, seg_ = e_ & 3;                                         \
            const uint8_t* g_ = (row_ < BM)                                            \
                ? g_Qf8 + (((size_t)(m0 + row_)) << 10) + kb_ + (seg_ << 4)            \
                : g_Kf8 + (((size_t)(n0 + row_ - BM)) << 10) + kb_ + (seg_ << 4);      \
            cp_async16(base_ + row_ * LDSB + (seg_ << 4), g_);                         \
        }                                                                              \
        CP_COMMIT();                                                                   \
    } while (0)

    LOAD_CHUNK(0, 0);
    LOAD_CHUNK(1, 1);
    LOAD_CHUNK(2, 2);

    for (int kt = 0; kt < NCHUNK; kt++) {
        const int st = kt % 3;
        if (kt < NCHUNK - 2)       asm volatile("cp.async.wait_group 2;\n" ::: "memory");
        else if (kt == NCHUNK - 2) asm volatile("cp.async.wait_group 1;\n" ::: "memory");
        else                       asm volatile("cp.async.wait_group 0;\n" ::: "memory");
        __syncthreads();

        const uint8_t* sA = smem + st * STAGE_BYTES;
        const uint8_t* sB = sA + BM * LDSB;

        #pragma unroll
        for (int ks = 0; ks < 2; ks++) {            // two k32 steps per 64B chunk
            const int kb = ks * 32;
            uint32_t a[4][4], bfr[4][2];
            #pragma unroll
            for (int mt = 0; mt < 4; mt++) {
                const uint8_t* p = sA + (wm + mt * 16 + (lane & 15)) * LDSB
                                      + kb + ((lane >> 4) << 4);
                uint32_t ad = (uint32_t)__cvta_generic_to_shared(p);
                asm volatile("ldmatrix.sync.aligned.m8n8.x4.shared.b16 {%0,%1,%2,%3}, [%4];\n"
                             : "=r"(a[mt][0]), "=r"(a[mt][1]), "=r"(a[mt][2]), "=r"(a[mt][3])
                             : "r"(ad));
            }
            #pragma unroll
            for (int np = 0; np < 2; np++) {        // 16 n-rows per x4
                const uint8_t* p = sB + (wn + np * 16 + (lane & 15)) * LDSB
                                      + kb + ((lane >> 4) << 4);
                uint32_t ad = (uint32_t)__cvta_generic_to_shared(p);
                uint32_t r0, r1, r2, r3;
                asm volatile("ldmatrix.sync.aligned.m8n8.x4.shared.b16 {%0,%1,%2,%3}, [%4];\n"
                             : "=r"(r0), "=r"(r1), "=r"(r2), "=r"(r3) : "r"(ad));
                bfr[np * 2][0]     = r0; bfr[np * 2][1]     = r2;
                bfr[np * 2 + 1][0] = r1; bfr[np * 2 + 1][1] = r3;
            }
            #pragma unroll
            for (int mt = 0; mt < 4; mt++)
                #pragma unroll
                for (int nt = 0; nt < 4; nt++)
                    mma_e4m3(acc[mt][nt], a[mt], bfr[nt]);
        }
        __syncthreads();
        if (kt + 3 < NCHUNK) LOAD_CHUNK(st, kt + 3);
    }
#undef LOAD_CHUNK

    // ---- stage sims tile into smem as sortable uint16 (pipeline stages are dead now) ----
    __syncthreads();
    uint16_t* sS = (uint16_t*)smem;     // [128][SIMS_STRIDE]
    #pragma unroll
    for (int mt = 0; mt < 4; mt++) {
        #pragma unroll
        for (int nt = 0; nt < 4; nt++) {
            int r0 = wm + mt * 16 + (lane >> 2);
            int cl = wn + nt * 8 + (lane & 3) * 2;
            uint32_t p0 = mono16(acc[mt][nt][0]) | (mono16(acc[mt][nt][1]) << 16);
            uint32_t p1 = mono16(acc[mt][nt][2]) | (mono16(acc[mt][nt][3]) << 16);
            *(uint32_t*)&sS[r0 * SIMS_STRIDE + cl]       = p0;
            *(uint32_t*)&sS[(r0 + 8) * SIMS_STRIDE + cl] = p1;
        }
    }
    __syncthreads();

    // ---- per-row top-8 over the 128 cols of this tile; warp w handles rows w*16..w*16+15 ----
    for (int rr = 0; rr < 16; rr++) {
        const int row = warp * 16 + rr;
        uint2 d = *(const uint2*)&sS[row * SIMS_STRIDE + lane * 4];
        const uint32_t cbase = (uint32_t)(n0 + lane * 4);
        uint32_t k0 = ((d.x & 0xFFFFu) << 16) | cbase;
        uint32_t k1 = (d.x & 0xFFFF0000u)     | (cbase + 1);
        uint32_t k2 = ((d.y & 0xFFFFu) << 16) | (cbase + 2);
        uint32_t k3 = (d.y & 0xFFFF0000u)     | (cbase + 3);
        uint32_t keep = 0;
        #pragma unroll
        for (int r = 0; r < PER_TILE; r++) {
            uint32_t b = max(max(k0, k1), max(k2, k3));
            #pragma unroll
            for (int o = 16; o; o >>= 1) {
                uint32_t ob = __shfl_xor_sync(0xFFFFFFFFu, b, o);
                b = max(b, ob);
            }
            if (k0 == b) k0 = 0;
            if (k1 == b) k1 = 0;
            if (k2 == b) k2 = 0;
            if (k3 == b) k3 = 0;
            if (lane == r) keep = b;
        }
        if (lane < PER_TILE)
            g_part[((size_t)(m0 + row)) * (NTILE * PER_TILE) + blockIdx.x * PER_TILE + lane] = keep;
    }
}

// ---------------- merge: per query, top-32 of the 4096 per-tile candidates ----------------
__global__ void merge_kernel() {
    const int q = blockIdx.x;
    const int t = threadIdx.x, lane = t & 31, warp = t >> 5;
    const uint4* p = (const uint4*)(g_part + (size_t)q * (NTILE * PER_TILE));

    // per-thread top-8 (sorted desc) over 16 entries (4 coalesced uint4 loads)
    uint32_t v[8];
    #pragma unroll
    for (int j = 0; j < 8; j++) v[j] = 0;
    #pragma unroll
    for (int j = 0; j < 4; j++) {
        uint4 d = p[t + (j << 8)];
        uint32_t e[4] = {d.x, d.y, d.z, d.w};
        #pragma unroll
        for (int s = 0; s < 4; s++) {
            uint32_t u = e[s];
            if (u > v[7]) {
                v[7] = u;
                #pragma unroll
                for (int jj = 7; jj > 0; jj--)
                    if (v[jj] > v[jj - 1]) { uint32_t tv = v[jj]; v[jj] = v[jj - 1]; v[jj - 1] = tv; }
            }
        }
    }

    // warp-local top-32 extraction (head pointer over sorted-desc v[]); no block syncs
    __shared__ uint32_t sw[256];
    int head = 0;
    uint32_t keep = 0;
    for (int r = 0; r < KCAND; r++) {
        uint32_t my = (head < 8) ? v[head] : 0;
        uint32_t b = my;
        #pragma unroll
        for (int o = 16; o; o >>= 1) b = max(b, __shfl_xor_sync(0xFFFFFFFFu, b, o));
        if (b != 0 && my == b) head++;
        if (lane == r) keep = b;
    }
    sw[warp * 32 + lane] = keep;
    __syncthreads();

    // warp 0 merges 8x32 survivors -> final top-32
    if (warp == 0) {
        uint32_t k2[8];
        #pragma unroll
        for (int j = 0; j < 8; j++) k2[j] = sw[lane + (j << 5)];
        uint32_t keep2 = 0;
        for (int r = 0; r < KCAND; r++) {
            uint32_t b = 0;
            #pragma unroll
            for (int j = 0; j < 8; j++) b = max(b, k2[j]);
            #pragma unroll
            for (int o = 16; o; o >>= 1) b = max(b, __shfl_xor_sync(0xFFFFFFFFu, b, o));
            #pragma unroll
            for (int j = 0; j < 8; j++)
                if (k2[j] == b) k2[j] = 0;
            if (lane == r) keep2 = b;
        }
        g_cand[q * KCAND + lane] = (int)(keep2 & 0xFFFFu);
    }
}

// ---------------- usage init: out_usage = memory_usage ----------------
__global__ void usage_init_kernel(const float* __restrict__ u, float* __restrict__ out_u) {
    int i = blockIdx.x * blockDim.x + threadIdx.x;
    out_u[i] = u[i];
}

// ---------------- exact fp32 rescore of 32 candidates + top-8 + gather + counts ----------------
__global__ void rescore_gather_kernel(const float* __restrict__ q,
                                      const float* __restrict__ keys,
                                      const float* __restrict__ vals,
                                      float* __restrict__ out_k,
                                      float* __restrict__ out_v,
                                      float* __restrict__ out_u) {
    const int b = blockIdx.x;
    const int t = threadIdx.x, lane = t & 31, w = t >> 5;
    __shared__ float qs[DIM];
    __shared__ float simv[KCAND];
    __shared__ int   simi[KCAND];
    __shared__ int   topi[KSEL];

    ((float4*)qs)[t] = ((const float4*)(q + (size_t)b * DIM))[t];
    __syncthreads();

    #pragma unroll
    for (int jj = 0; jj < 4; jj++) {
        int j = w * 4 + jj;
        int c = g_cand[b * KCAND + j];
        const float* kr = keys + (size_t)c * DIM;
        float s = 0.f;
        #pragma unroll 8
        for (int i = lane; i < DIM; i += 32) s = fmaf(qs[i], kr[i], s);
        #pragma unroll
        for (int o = 16; o; o >>= 1) s += __shfl_xor_sync(0xFFFFFFFFu, s, o);
        if (lane == 0) { simv[j] = s * g_rnorm[c]; simi[j] = c; }
    }
    __syncthreads();

    if (t == 0) {
        unsigned used = 0;
        for (int r = 0; r < KSEL; r++) {
            int best = -1;
            for (int j = 0; j < KCAND; j++) {
                if (used & (1u << j)) continue;
                if (best < 0 || simv[j] > simv[best] ||
                    (simv[j] == simv[best] && simi[j] < simi[best])) best = j;
            }
            used |= 1u << best;
            topi[r] = simi[best];
        }
    }
    __syncthreads();

    for (int r = 0; r < KSEL; r++) {
        int c = topi[r];
        const float4* sk = (const float4*)(keys + (size_t)c * DIM);
        const float4* sw = (const float4*)(vals + (size_t)c * DIM);
        float4* dk = (float4*)(out_k + ((size_t)b * KSEL + r) * DIM);
        float4* dv = (float4*)(out_v + ((size_t)b * KSEL + r) * DIM);
        dk[t] = sk[t];
        dv[t] = sw[t];
    }
    if (t < KSEL) atomicAdd(&out_u[topi[t]], 1.0f);
}

// ---------------- launch ----------------
extern "C" void kernel_launch(void* const* d_in, const int* in_sizes, int n_in,
                              void* d_out, int out_size) {
    const float* query  = (const float*)d_in[0];
    const float* keys   = (const float*)d_in[1];
    const float* values = (const float*)d_in[2];
    const float* usage  = (const float*)d_in[3];
    // d_in[4] = k (fixed to 8 by problem shape / out_size)

    float* out       = (float*)d_out;
    float* out_keys  = out;
    float* out_vals  = out + (size_t)BQ * KSEL * DIM;
    float* out_usage = out + (size_t)2 * BQ * KSEL * DIM;

    cudaFuncSetAttribute(gemm_kernel, cudaFuncAttributeMaxDynamicSharedMemorySize, SMEM_DYN);

    prep_q_kernel<<<(BQ * DIM / 4) / 256, 256>>>((const float4*)query);
    prep_keys_kernel<<<CC, 256>>>(keys);

    dim3 ggrid(CC / BN, BQ / BM);       // (512, 16)
    gemm_kernel<<<ggrid, 256, SMEM_DYN>>>();

    merge_kernel<<<BQ, 256>>>();
    usage_init_kernel<<<CC / 256, 256>>>(usage, out_usage);
    rescore_gather_kernel<<<BQ, 256>>>(query, keys, values, out_keys, out_vals, out_usage);
}